// round 1
// baseline (speedup 1.0000x reference)
#include <cuda_runtime.h>
#include <math.h>

#define K_VOX 40000
#define T_PTS 35
#define C_IN  7
#define U1    16
#define U1P   17   // padded stride to avoid smem bank conflicts
#define U2    32
#define DD    10
#define HH    400
#define WW    352
#define NROWS (K_VOX * T_PTS)
#define EPSBN 1e-5f
#define WARPS_PER_BLOCK 8

// ---------------- global scratch (allocation-free) ----------------
__device__ float g_sum1[U1];
__device__ float g_sq1 [U1];
__device__ float g_sum2[U2];
__device__ float g_sq2 [U2];

__global__ void zero_stats_kernel() {
    int t = threadIdx.x;
    if (t < U1)                 { g_sum1[t] = 0.f; }
    else if (t < 2*U1)          { g_sq1 [t - U1] = 0.f; }
    else if (t < 2*U1 + U2)     { g_sum2[t - 2*U1] = 0.f; }
    else if (t < 2*U1 + 2*U2)   { g_sq2 [t - 2*U1 - U2] = 0.f; }
}

// ---------------- pass 1: layer-1 BN statistics ----------------
__global__ void stats1_kernel(const float* __restrict__ feat,
                              const float* __restrict__ w1,
                              const float* __restrict__ b1) {
    __shared__ float sw[C_IN * U1];
    __shared__ float sb[U1];
    __shared__ float ssum[U1], ssq[U1];
    int tid = threadIdx.x;
    if (tid < C_IN * U1) sw[tid] = w1[tid];
    if (tid < U1) { sb[tid] = b1[tid]; ssum[tid] = 0.f; ssq[tid] = 0.f; }
    __syncthreads();

    float psum[U1], psq[U1];
#pragma unroll
    for (int u = 0; u < U1; u++) { psum[u] = 0.f; psq[u] = 0.f; }

    for (int r = blockIdx.x * blockDim.x + tid; r < NROWS;
         r += gridDim.x * blockDim.x) {
        float f[C_IN];
        const float* fp = feat + (long)r * C_IN;
#pragma unroll
        for (int c = 0; c < C_IN; c++) f[c] = fp[c];
#pragma unroll
        for (int u = 0; u < U1; u++) {
            float a = sb[u];
#pragma unroll
            for (int c = 0; c < C_IN; c++) a = fmaf(f[c], sw[c * U1 + u], a);
            a = fmaxf(a, 0.f);
            psum[u] += a;
            psq [u] += a * a;
        }
    }
#pragma unroll
    for (int u = 0; u < U1; u++) {
#pragma unroll
        for (int o = 16; o > 0; o >>= 1) {
            psum[u] += __shfl_down_sync(0xFFFFFFFFu, psum[u], o);
            psq [u] += __shfl_down_sync(0xFFFFFFFFu, psq [u], o);
        }
        if ((tid & 31) == 0) {
            atomicAdd(&ssum[u], psum[u]);
            atomicAdd(&ssq [u], psq [u]);
        }
    }
    __syncthreads();
    if (tid < U1) {
        atomicAdd(&g_sum1[tid], ssum[tid]);
        atomicAdd(&g_sq1 [tid], ssq [tid]);
    }
}

// ---------------- fused voxel kernel ----------------
// PASS==2: compute layer-2 BN statistics.
// PASS==3: full forward + voxelwise max + scatter-add into output grid.
template <int PASS>
__global__ void voxel_kernel(const float* __restrict__ feat,
                             const float* __restrict__ w1,
                             const float* __restrict__ b1,
                             const float* __restrict__ g1,
                             const float* __restrict__ be1,
                             const float* __restrict__ w2,
                             const float* __restrict__ b2,
                             const float* __restrict__ g2,
                             const float* __restrict__ be2,
                             const int*   __restrict__ coord,
                             float*       __restrict__ out) {
    __shared__ float sw1[C_IN * U1];
    __shared__ float sb1[U1];
    __shared__ float s_sc1[U1], s_sh1[U1];
    __shared__ float s_sc2[U2], s_sh2[U2];
    __shared__ float s_h1  [WARPS_PER_BLOCK][T_PTS][U1P];
    __shared__ float s_mask[WARPS_PER_BLOCK][T_PTS];
    __shared__ float s_agg1[WARPS_PER_BLOCK][U1];
    __shared__ float s_acc [U2], s_accq[U2];

    const int tid  = threadIdx.x;
    const int w    = tid >> 5;
    const int lane = tid & 31;
    const float invN = 1.0f / (float)NROWS;

    if (tid < C_IN * U1) sw1[tid] = w1[tid];
    if (tid < U1) {
        sb1[tid] = b1[tid];
        float mean = g_sum1[tid] * invN;
        float var  = g_sq1[tid] * invN - mean * mean;
        float rs   = rsqrtf(var + EPSBN);
        float sc   = rs * g1[tid];
        s_sc1[tid] = sc;
        s_sh1[tid] = be1[tid] - mean * sc;
    }
    if (PASS == 3) {
        if (tid >= 64 && tid < 64 + U2) {
            int l = tid - 64;
            float mean = g_sum2[l] * invN;
            float var  = g_sq2[l] * invN - mean * mean;
            float rs   = rsqrtf(var + EPSBN);
            float sc   = rs * g2[l];
            s_sc2[l] = sc;
            s_sh2[l] = be2[l] - mean * sc;
        }
    } else {
        if (tid >= 64 && tid < 64 + U2) {
            int l = tid - 64;
            s_acc[l] = 0.f; s_accq[l] = 0.f;
        }
    }
    __syncthreads();

    const int v = blockIdx.x * WARPS_PER_BLOCK + w;
    if (v < K_VOX) {
        // ---- phase A: layer 1 per point row, normalized, into shared ----
        const float* fv = feat + (long)v * T_PTS * C_IN;
        for (int t = lane; t < T_PTS; t += 32) {
            float f[C_IN];
            float maxc = -INFINITY;
#pragma unroll
            for (int c = 0; c < C_IN; c++) {
                f[c] = fv[t * C_IN + c];
                maxc = fmaxf(maxc, f[c]);
            }
            s_mask[w][t] = (maxc != 0.0f) ? 1.0f : 0.0f;
#pragma unroll
            for (int u = 0; u < U1; u++) {
                float a = sb1[u];
#pragma unroll
                for (int c = 0; c < C_IN; c++) a = fmaf(f[c], sw1[c * U1 + u], a);
                a = fmaxf(a, 0.f);                     // relu
                s_h1[w][t][u] = a * s_sc1[u] + s_sh1[u]; // BN folded
            }
        }
        __syncwarp();

        // ---- phase B: agg1[u] = max over t ----
        if (lane < U1) {
            float mx = -INFINITY;
            for (int t = 0; t < T_PTS; t++) mx = fmaxf(mx, s_h1[w][t][lane]);
            s_agg1[w][lane] = mx;
        }
        __syncwarp();

        // ---- phase C: layer 2, lane = output channel ----
        float wcol[U2];
#pragma unroll
        for (int i = 0; i < U2; i++) wcol[i] = w2[i * U2 + lane];
        float aggdot = 0.f;
#pragma unroll
        for (int j = 0; j < U1; j++)
            aggdot = fmaf(s_agg1[w][j], wcol[U1 + j], aggdot);
        const float b2l = b2[lane];

        if (PASS == 2) {
            float sum = 0.f, sq = 0.f;
            for (int t = 0; t < T_PTS; t++) {
                float m = s_mask[w][t];
                float dot = 0.f;
#pragma unroll
                for (int i = 0; i < U1; i++)
                    dot = fmaf(s_h1[w][t][i], wcol[i], dot);
                float h2 = fmaxf(b2l + m * (dot + aggdot), 0.f);
                sum += h2;
                sq  += h2 * h2;
            }
            atomicAdd(&s_acc [lane], sum);
            atomicAdd(&s_accq[lane], sq);
        } else {
            const float sc2l = s_sc2[lane];
            const float sh2l = s_sh2[lane];
            float agg2 = -INFINITY;
            float vwlo = -INFINITY;
            bool anyM = false, allM = true;
            for (int t = 0; t < T_PTS; t++) {
                float m = s_mask[w][t];
                float dot = 0.f;
#pragma unroll
                for (int i = 0; i < U1; i++)
                    dot = fmaf(s_h1[w][t][i], wcol[i], dot);
                float h2  = fmaxf(b2l + m * (dot + aggdot), 0.f);
                float h2n = h2 * sc2l + sh2l;
                agg2 = fmaxf(agg2, h2n);
                vwlo = fmaxf(vwlo, m * h2n);
                bool mb = (m != 0.f);
                anyM = anyM || mb;
                allM = allM && mb;
            }
            float vwhi;
            if (!anyM)      vwhi = 0.f;
            else if (allM)  vwhi = agg2;
            else            vwhi = fmaxf(agg2, 0.f);

            const int* cp = coord + (long)v * 4;
            long base = ((((long)cp[0] * DD + cp[1]) * HH + cp[2]) * WW + cp[3]) * 64;
            atomicAdd(out + base + lane,      vwlo);
            atomicAdd(out + base + 32 + lane, vwhi);
        }
    }

    if (PASS == 2) {
        __syncthreads();
        if (tid < U2) {
            atomicAdd(&g_sum2[tid], s_acc [tid]);
            atomicAdd(&g_sq2 [tid], s_accq[tid]);
        }
    }
}

// ---------------- launch ----------------
extern "C" void kernel_launch(void* const* d_in, const int* in_sizes, int n_in,
                              void* d_out, int out_size) {
    const float* feat  = (const float*)d_in[0];
    const float* w1    = (const float*)d_in[1];
    const float* b1    = (const float*)d_in[2];
    const float* g1    = (const float*)d_in[3];
    const float* be1   = (const float*)d_in[4];
    const float* w2    = (const float*)d_in[5];
    const float* b2    = (const float*)d_in[6];
    const float* g2    = (const float*)d_in[7];
    const float* be2   = (const float*)d_in[8];
    const int*   coord = (const int*)  d_in[9];
    float* out = (float*)d_out;

    // zero the (poisoned) output grid — dominates runtime, pure HBM write
    cudaMemsetAsync(d_out, 0, (size_t)out_size * sizeof(float), 0);

    zero_stats_kernel<<<1, 96>>>();
    stats1_kernel<<<1184, 256>>>(feat, w1, b1);

    const int nblk = (K_VOX + WARPS_PER_BLOCK - 1) / WARPS_PER_BLOCK; // 5000
    voxel_kernel<2><<<nblk, 32 * WARPS_PER_BLOCK>>>(
        feat, w1, b1, g1, be1, w2, b2, g2, be2, coord, out);
    voxel_kernel<3><<<nblk, 32 * WARPS_PER_BLOCK>>>(
        feat, w1, b1, g1, be1, w2, b2, g2, be2, coord, out);
}

// round 2
// speedup vs baseline: 1.7641x; 1.7641x over previous
#include <cuda_runtime.h>
#include <math.h>

#define K_VOX 40000
#define T_PTS 35
#define C_IN  7
#define U1    16
#define U2    32
#define DD    10
#define HH    400
#define WW    352
#define NROWS (K_VOX * T_PTS)
#define EPSBN 1e-5f

#define NBLK   148
#define NTHR   256
#define NWARP  8
#define CWARPS 6      // compute warps per block (stage 2)
#define ZWARPS 2      // zeroing warps per block (stage 2)
#define H1S    20     // h1 row stride in floats (conflict-free 16B STS/LDS)

// ---------------- global scratch (static, allocation-free) ----------------
__device__ float    g_sum1[U1], g_sq1[U1];
__device__ float    g_sum2[U2], g_sq2[U2];
__device__ unsigned g_bar;
__device__ float    g_vox[(size_t)K_VOX * 4 * U2];   // [v][{Mx,Mn,Mx1,Mn1}][32]
__device__ int      g_flags[K_VOX];                  // bit0 anyM, bit1 allM

__global__ void zero_stats_kernel() {
    int t = threadIdx.x;
    if (t < U1) { g_sum1[t] = 0.f; g_sq1[t] = 0.f; }
    if (t < U2) { g_sum2[t] = 0.f; g_sq2[t] = 0.f; }
    if (t == 0) g_bar = 0u;
}

// grid-wide barrier: all NBLK blocks resident by construction (1 block/SM).
__device__ __forceinline__ void gsync(unsigned target) {
    __syncthreads();
    if (threadIdx.x == 0) {
        __threadfence();
        atomicAdd(&g_bar, 1u);
        while (*((volatile unsigned*)&g_bar) < target) { }
        __threadfence();
    }
    __syncthreads();
}

__global__ void __launch_bounds__(NTHR, 1)
fused_kernel(const float* __restrict__ feat,
             const float* __restrict__ w1,  const float* __restrict__ b1,
             const float* __restrict__ g1,  const float* __restrict__ be1,
             const float* __restrict__ w2,  const float* __restrict__ b2,
             const float* __restrict__ g2,  const float* __restrict__ be2,
             const int*   __restrict__ coord,
             float*       __restrict__ out, int out_size) {
    __shared__ float sw1[C_IN * U1];
    __shared__ float sb1[U1];
    __shared__ float s_sc1[U1], s_sh1[U1];
    __shared__ float s_sc2[U2], s_sh2[U2];
    __shared__ float ssum[U1], ssq[U1];
    __shared__ float s_h1[CWARPS][T_PTS][H1S];
    __shared__ float s_mask[CWARPS][T_PTS];
    __shared__ float s_agg[CWARPS][U1];

    const int tid  = threadIdx.x;
    const int w    = tid >> 5;
    const int lane = tid & 31;
    const float invN = 1.0f / (float)NROWS;

    if (tid < C_IN * U1) sw1[tid] = w1[tid];
    if (tid < U1) { sb1[tid] = b1[tid]; ssum[tid] = 0.f; ssq[tid] = 0.f; }
    __syncthreads();

    // ================= stage 1: BN1 statistics =================
    {
        float psum[U1], psq[U1];
#pragma unroll
        for (int u = 0; u < U1; u++) { psum[u] = 0.f; psq[u] = 0.f; }
        for (int r = blockIdx.x * NTHR + tid; r < NROWS; r += NBLK * NTHR) {
            const float* fp = feat + (size_t)r * C_IN;
            float f[C_IN];
#pragma unroll
            for (int c = 0; c < C_IN; c++) f[c] = fp[c];
#pragma unroll
            for (int u = 0; u < U1; u++) {
                float a = sb1[u];
#pragma unroll
                for (int c = 0; c < C_IN; c++) a = fmaf(f[c], sw1[c * U1 + u], a);
                a = fmaxf(a, 0.f);
                psum[u] += a;
                psq [u] = fmaf(a, a, psq[u]);
            }
        }
#pragma unroll
        for (int u = 0; u < U1; u++) {
#pragma unroll
            for (int o = 16; o > 0; o >>= 1) {
                psum[u] += __shfl_down_sync(0xFFFFFFFFu, psum[u], o);
                psq [u] += __shfl_down_sync(0xFFFFFFFFu, psq [u], o);
            }
            if (lane == 0) {
                atomicAdd(&ssum[u], psum[u]);
                atomicAdd(&ssq [u], psq [u]);
            }
        }
        __syncthreads();
        if (tid < U1) {
            atomicAdd(&g_sum1[tid], ssum[tid]);
            atomicAdd(&g_sq1 [tid], ssq [tid]);
        }
    }
    gsync(NBLK);   // all BN1 stats visible

    // fold BN1 into scale/shift
    if (tid < U1) {
        float mean = __ldcg(&g_sum1[tid]) * invN;
        float var  = __ldcg(&g_sq1 [tid]) * invN - mean * mean;
        float sc   = rsqrtf(var + EPSBN) * g1[tid];
        s_sc1[tid] = sc;
        s_sh1[tid] = be1[tid] - mean * sc;
    }
    __syncthreads();

    // ================= stage 2: voxel pass (warps 0-5)  ||  zero out (warps 6-7) ===========
    if (w < CWARPS) {
        // per-warp invariants
        float wcol[U2];
#pragma unroll
        for (int i = 0; i < U2; i++) wcol[i] = w2[i * U2 + lane];
        const float b2l = b2[lane];

        float vsum = 0.f, vsq = 0.f;

        for (int v = blockIdx.x * CWARPS + w; v < K_VOX; v += NBLK * CWARPS) {
            const float* fv = feat + (size_t)v * T_PTS * C_IN;

            // ---- phase A: layer 1 (lane = t) ----
            unsigned mb0, mb1;
            {
                int t = lane;   // t < 32 always valid
                const float* fp = fv + t * C_IN;
                float f[C_IN]; float mx = -INFINITY;
#pragma unroll
                for (int c = 0; c < C_IN; c++) { f[c] = fp[c]; mx = fmaxf(mx, f[c]); }
                float m = (mx != 0.0f) ? 1.0f : 0.0f;
                mb0 = __ballot_sync(0xFFFFFFFFu, m != 0.0f);
                s_mask[w][t] = m;
                float h[U1];
#pragma unroll
                for (int u = 0; u < U1; u++) {
                    float a = sb1[u];
#pragma unroll
                    for (int c = 0; c < C_IN; c++) a = fmaf(f[c], sw1[c * U1 + u], a);
                    a = fmaxf(a, 0.f);
                    h[u] = fmaf(a, s_sc1[u], s_sh1[u]);
                }
                float4* row = (float4*)&s_h1[w][t][0];
                row[0] = make_float4(h[0],  h[1],  h[2],  h[3]);
                row[1] = make_float4(h[4],  h[5],  h[6],  h[7]);
                row[2] = make_float4(h[8],  h[9],  h[10], h[11]);
                row[3] = make_float4(h[12], h[13], h[14], h[15]);
            }
            {
                int t = 32 + lane;
                bool act = (lane < (T_PTS - 32));
                float m = 0.0f;
                float f[C_IN];
                if (act) {
                    const float* fp = fv + t * C_IN;
                    float mx = -INFINITY;
#pragma unroll
                    for (int c = 0; c < C_IN; c++) { f[c] = fp[c]; mx = fmaxf(mx, f[c]); }
                    m = (mx != 0.0f) ? 1.0f : 0.0f;
                }
                mb1 = __ballot_sync(0xFFFFFFFFu, act && (m != 0.0f));
                if (act) {
                    s_mask[w][t] = m;
                    float h[U1];
#pragma unroll
                    for (int u = 0; u < U1; u++) {
                        float a = sb1[u];
#pragma unroll
                        for (int c = 0; c < C_IN; c++) a = fmaf(f[c], sw1[c * U1 + u], a);
                        a = fmaxf(a, 0.f);
                        h[u] = fmaf(a, s_sc1[u], s_sh1[u]);
                    }
                    float4* row = (float4*)&s_h1[w][t][0];
                    row[0] = make_float4(h[0],  h[1],  h[2],  h[3]);
                    row[1] = make_float4(h[4],  h[5],  h[6],  h[7]);
                    row[2] = make_float4(h[8],  h[9],  h[10], h[11]);
                    row[3] = make_float4(h[12], h[13], h[14], h[15]);
                }
            }
            const bool anyM = ((mb0 | (mb1 & 7u)) != 0u);
            const bool allM = (mb0 == 0xFFFFFFFFu) && ((mb1 & 7u) == 7u);
            __syncwarp();

            // ---- phase B: agg1 over t ----
            if (lane < U1) {
                float mx = -INFINITY;
                for (int t = 0; t < T_PTS; t++) mx = fmaxf(mx, s_h1[w][t][lane]);
                s_agg[w][lane] = mx;
            }
            __syncwarp();

            // ---- phase C: layer 2 (lane = output channel) ----
            float aggdot = 0.f;
#pragma unroll
            for (int j = 0; j < U1; j++)
                aggdot = fmaf(s_agg[w][j], wcol[U1 + j], aggdot);

            float Mx = -INFINITY, Mn = INFINITY;
            float Mx1 = -INFINITY, Mn1 = INFINITY;
#pragma unroll 5
            for (int t = 0; t < T_PTS; t++) {
                const float4* row = (const float4*)&s_h1[w][t][0];
                float4 a0 = row[0], a1 = row[1], a2 = row[2], a3 = row[3];
                float d0 = a0.x * wcol[0];
                float d1 = a0.y * wcol[1];
                d0 = fmaf(a0.z, wcol[2],  d0); d1 = fmaf(a0.w, wcol[3],  d1);
                d0 = fmaf(a1.x, wcol[4],  d0); d1 = fmaf(a1.y, wcol[5],  d1);
                d0 = fmaf(a1.z, wcol[6],  d0); d1 = fmaf(a1.w, wcol[7],  d1);
                d0 = fmaf(a2.x, wcol[8],  d0); d1 = fmaf(a2.y, wcol[9],  d1);
                d0 = fmaf(a2.z, wcol[10], d0); d1 = fmaf(a2.w, wcol[11], d1);
                d0 = fmaf(a3.x, wcol[12], d0); d1 = fmaf(a3.y, wcol[13], d1);
                d0 = fmaf(a3.z, wcol[14], d0); d1 = fmaf(a3.w, wcol[15], d1);
                float m  = s_mask[w][t];
                float h2 = fmaxf(fmaf(m, d0 + d1 + aggdot, b2l), 0.f);
                vsum += h2;
                vsq   = fmaf(h2, h2, vsq);
                Mx = fmaxf(Mx, h2);
                Mn = fminf(Mn, h2);
                bool mb = (m != 0.f);
                Mx1 = fmaxf(Mx1, mb ? h2 : -INFINITY);
                Mn1 = fminf(Mn1, mb ? h2 :  INFINITY);
            }

            float* gv = g_vox + (size_t)v * (4 * U2);
            gv[lane]           = Mx;
            gv[U2 + lane]      = Mn;
            gv[2 * U2 + lane]  = Mx1;
            gv[3 * U2 + lane]  = Mn1;
            if (lane == 0) g_flags[v] = (anyM ? 1 : 0) | (allM ? 2 : 0);
        }
        atomicAdd(&g_sum2[lane], vsum);
        atomicAdd(&g_sq2 [lane], vsq);
    } else {
        // ---- zero the 721MB output grid (pure HBM stream) ----
        const int zid  = blockIdx.x * (ZWARPS * 32) + (w - CWARPS) * 32 + lane;
        const int n4   = out_size >> 2;
        float4 z4 = make_float4(0.f, 0.f, 0.f, 0.f);
        float4* o4 = (float4*)out;
        for (int i = zid; i < n4; i += NBLK * ZWARPS * 32) o4[i] = z4;
        for (int i = (n4 << 2) + zid; i < out_size; i += NBLK * ZWARPS * 32) out[i] = 0.f;
    }
    gsync(2 * NBLK);   // zeros + BN2 stats + g_vox all visible

    // ================= stage 3: finalize + scatter =================
    if (tid < U2) {
        float mean = __ldcg(&g_sum2[tid]) * invN;
        float var  = __ldcg(&g_sq2 [tid]) * invN - mean * mean;
        float sc   = rsqrtf(var + EPSBN) * g2[tid];
        s_sc2[tid] = sc;
        s_sh2[tid] = be2[tid] - mean * sc;
    }
    __syncthreads();

    {
        const float sc = s_sc2[lane];
        const float sh = s_sh2[lane];
        for (int v = blockIdx.x * NWARP + w; v < K_VOX; v += NBLK * NWARP) {
            const float* gv = g_vox + (size_t)v * (4 * U2);
            float Mx  = __ldcg(gv + lane);
            float Mn  = __ldcg(gv + U2 + lane);
            float Mx1 = __ldcg(gv + 2 * U2 + lane);
            float Mn1 = __ldcg(gv + 3 * U2 + lane);
            int   fl  = g_flags[v];
            bool anyM = (fl & 1) != 0;
            bool allM = (fl & 2) != 0;

            float agg2 = fmaf((sc >= 0.f) ? Mx  : Mn,  sc, sh);
            float mskd = fmaf((sc >= 0.f) ? Mx1 : Mn1, sc, sh);

            float vwlo = anyM ? mskd : -INFINITY;
            float vwhi = anyM ? agg2 : -INFINITY;
            if (!allM) { vwlo = fmaxf(vwlo, 0.f); vwhi = fmaxf(vwhi, 0.f); }

            const int* cp = coord + (size_t)v * 4;
            size_t base = ((((size_t)cp[0] * DD + cp[1]) * HH + cp[2]) * WW + cp[3]) * (size_t)(2 * U2);
            atomicAdd(out + base + lane,      vwlo);
            atomicAdd(out + base + U2 + lane, vwhi);
        }
    }
}

// ---------------- launch ----------------
extern "C" void kernel_launch(void* const* d_in, const int* in_sizes, int n_in,
                              void* d_out, int out_size) {
    const float* feat  = (const float*)d_in[0];
    const float* w1    = (const float*)d_in[1];
    const float* b1    = (const float*)d_in[2];
    const float* g1    = (const float*)d_in[3];
    const float* be1   = (const float*)d_in[4];
    const float* w2    = (const float*)d_in[5];
    const float* b2    = (const float*)d_in[6];
    const float* g2    = (const float*)d_in[7];
    const float* be2   = (const float*)d_in[8];
    const int*   coord = (const int*)  d_in[9];
    float* out = (float*)d_out;

    zero_stats_kernel<<<1, 64>>>();
    fused_kernel<<<NBLK, NTHR>>>(feat, w1, b1, g1, be1,
                                 w2, b2, g2, be2, coord, out, out_size);
}